// round 17
// baseline (speedup 1.0000x reference)
#include <cuda_runtime.h>

#define C_CLASS 32
#define S_SUP   16
#define D_DIM   1024
#define QB      8          // queries per CTA (2 warps per query: d-split)
#define THREADS 512

// smem: scaled support [16][1024] + wsm2 (8q x 16 u64) + psm (8q x 16 partials)
#define SMEM_FLOATS (S_SUP*D_DIM + 2*QB*S_SUP + QB*S_SUP + 16)
#define SMEM_BYTES  (SMEM_FLOATS * 4)

using u64 = unsigned long long;

__device__ __forceinline__ float fex2(float x){ float y; asm("ex2.approx.f32 %0,%1;" : "=f"(y) : "f"(x)); return y; }
__device__ __forceinline__ float frcp(float x){ float y; asm("rcp.approx.f32 %0,%1;" : "=f"(y) : "f"(x)); return y; }
__device__ __forceinline__ u64 mul2(u64 a, u64 b){ u64 r; asm("mul.rn.f32x2 %0,%1,%2;" : "=l"(r) : "l"(a), "l"(b)); return r; }
__device__ __forceinline__ u64 fma2(u64 a, u64 b, u64 c){ u64 r; asm("fma.rn.f32x2 %0,%1,%2,%3;" : "=l"(r) : "l"(a), "l"(b), "l"(c)); return r; }
__device__ __forceinline__ void unpack2(u64 p, float& lo, float& hi){ asm("mov.b64 {%0,%1},%2;" : "=f"(lo), "=f"(hi) : "l"(p)); }
__device__ __forceinline__ u64 pack2(float lo, float hi){ u64 p; asm("mov.b64 %0,{%1,%2};" : "=l"(p) : "f"(lo), "f"(hi)); return p; }

// Build N8, P8 for 8 elements of one support row such that
// sum_{i<8} 1/d_i = N8 / P8, d_i = 1 + 2^{z_i}, z_i = s_i*q_i (pre-scaled).
// z packed via mul.rn.f32x2 (operands LDS.128-adjacent; unpack = aliasing).
// No clamp: max |z| ~ 56 for N(0,1) data; d_i >= 1 so P never underflows.
__device__ __forceinline__ void np8(float& N8, float& P8,
                                    ulonglong2 sa, ulonglong2 sb,
                                    ulonglong2 qa, ulonglong2 qb) {
    u64 z01 = mul2(sa.x, qa.x);
    u64 z23 = mul2(sa.y, qa.y);
    u64 z45 = mul2(sb.x, qb.x);
    u64 z67 = mul2(sb.y, qb.y);
    float z0, z1, z2, z3, z4, z5, z6, z7;
    unpack2(z01, z0, z1);
    unpack2(z23, z2, z3);
    unpack2(z45, z4, z5);
    unpack2(z67, z6, z7);
    float d0 = 1.0f + fex2(z0);
    float d1 = 1.0f + fex2(z1);
    float d2 = 1.0f + fex2(z2);
    float d3 = 1.0f + fex2(z3);
    float d4 = 1.0f + fex2(z4);
    float d5 = 1.0f + fex2(z5);
    float d6 = 1.0f + fex2(z6);
    float d7 = 1.0f + fex2(z7);
    float p01 = d0 * d1, p23 = d2 * d3, p45 = d4 * d5, p67 = d6 * d7;
    float N4a = fmaf(p01, d2 + d3, p23 * (d0 + d1));
    float N4b = fmaf(p45, d6 + d7, p67 * (d4 + d5));
    float P4a = p01 * p23, P4b = p45 * p67;
    N8 = fmaf(N4a, P4b, N4b * P4a);
    P8 = P4a * P4b;
}

__global__ __launch_bounds__(THREADS, 2)
void instance_attention_kernel(const float* __restrict__ data,
                               float* __restrict__ out)
{
    extern __shared__ float sm[];
    float* cs   = sm;                            // support * (-2*log2e) [16][1024]
    u64*   wsm2 = (u64*)(sm + S_SUP*D_DIM);      // [8][16] duplicated weight pairs
    float* psm  = sm + S_SUP*D_DIM + 2*QB*S_SUP; // [8][16] d-half-1 partial scores

    const int c    = blockIdx.y;
    const int qb   = blockIdx.x;
    const int tid  = threadIdx.x;
    const int w    = tid >> 5;
    const int lane = tid & 31;
    const int ql    = w & 7;     // query owned by this warp
    const int dhalf = w >> 3;    // which 512-elem half of the feature dim

    const float HSCALE   = -2.885390081777927f;   // -2*log2(e)
    const float TWOLOG2E =  2.885390081777927f;   // softmax fold (score = 2a + const)
    const float DESCALE  = -0.34657359027997264f; // 1/HSCALE: undo support pre-scale

    // ---- load scaled support tile ----
    const float4* supg = (const float4*)(data + (size_t)(c * S_SUP) * D_DIM);
    float4* cs4 = (float4*)cs;
    #pragma unroll
    for (int i = tid; i < S_SUP * D_DIM / 4; i += THREADS) {
        float4 v = supg[i];
        v.x *= HSCALE; v.y *= HSCALE; v.z *= HSCALE; v.w *= HSCALE;
        cs4[i] = v;
    }
    __syncthreads();

    const int qglob = qb * QB + ql;
    const ulonglong2* qg2 = (const ulonglong2*)(data + (size_t)(C_CLASS * S_SUP + qglob) * D_DIM);
    const ulonglong2* cs_u2 = (const ulonglong2*)cs;

    // ---- scoring: this warp covers elements [dhalf*512, dhalf*512+512) ----
    float acc[16];
    #pragma unroll
    for (int r = 0; r < 16; ++r) acc[r] = 0.0f;

    {
        ulonglong2 qv[4];
        #pragma unroll
        for (int it = 0; it < 4; ++it) qv[it] = qg2[(dhalf * 4 + it) * 32 + lane];
        #pragma unroll
        for (int ot = 0; ot < 2; ++ot) {
            const int i0 = (dhalf * 2 + ot) * 64 + lane;  // u2-granularity index
            const int i1 = i0 + 32;
            const ulonglong2 qa  = qv[2 * ot];
            const ulonglong2 qbv = qv[2 * ot + 1];
            // row PAIRS share one reciprocal (R15-proven)
            #pragma unroll
            for (int rp = 0; rp < 8; ++rp) {
                const ulonglong2* rowA = cs_u2 + (2 * rp)     * (D_DIM / 4);
                const ulonglong2* rowB = cs_u2 + (2 * rp + 1) * (D_DIM / 4);
                float N8a, P8a, N8b, P8b;
                np8(N8a, P8a, rowA[i0], rowA[i1], qa, qbv);
                np8(N8b, P8b, rowB[i0], rowB[i1], qa, qbv);
                float rc   = frcp(P8a * P8b);
                float invA = P8b * rc;
                float invB = P8a * rc;
                acc[2 * rp]     = fmaf(N8a, invA, acc[2 * rp]);
                acc[2 * rp + 1] = fmaf(N8b, invB, acc[2 * rp + 1]);
            }
        }
    }

    // ---- register-halving transpose-reduce (R16-proven): lane l ends with
    //      this warp's partial sum for row (l & 15), duplicated across halves ----
    float t8[8];
    {
        const bool hb = (lane & 1);
        #pragma unroll
        for (int k = 0; k < 8; ++k) {
            float send = hb ? acc[2*k]   : acc[2*k+1];
            float keep = hb ? acc[2*k+1] : acc[2*k];
            t8[k] = keep + __shfl_xor_sync(0xffffffffu, send, 1);
        }
    }
    float t4[4];
    {
        const bool hb = (lane & 2);
        #pragma unroll
        for (int k = 0; k < 4; ++k) {
            float send = hb ? t8[2*k]   : t8[2*k+1];
            float keep = hb ? t8[2*k+1] : t8[2*k];
            t4[k] = keep + __shfl_xor_sync(0xffffffffu, send, 2);
        }
    }
    float t2[2];
    {
        const bool hb = (lane & 4);
        #pragma unroll
        for (int k = 0; k < 2; ++k) {
            float send = hb ? t4[2*k]   : t4[2*k+1];
            float keep = hb ? t4[2*k+1] : t4[2*k];
            t2[k] = keep + __shfl_xor_sync(0xffffffffu, send, 4);
        }
    }
    float x;
    {
        const bool hb = (lane & 8);
        float send = hb ? t2[0] : t2[1];
        float keep = hb ? t2[1] : t2[0];
        x = keep + __shfl_xor_sync(0xffffffffu, send, 8);
    }
    x += __shfl_xor_sync(0xffffffffu, x, 16);   // warp partial for row (lane&15)

    // d-half 1 publishes its partials; d-half 0 combines + softmax
    if (dhalf == 1 && lane < 16) psm[ql * 16 + lane] = x;
    __syncthreads();

    if (dhalf == 0) {
        x += psm[ql * 16 + (lane & 15)];        // full score accumulator
        // lane-parallel softmax over 16 rows (offsets within 16-lane halves)
        // score = 2a - 1024 (affine): factor 2 folds into TWOLOG2E.
        float m = x;
        #pragma unroll
        for (int off = 8; off; off >>= 1)
            m = fmaxf(m, __shfl_xor_sync(0xffffffffu, m, off));
        float e = fex2((x - m) * TWOLOG2E);
        float ssum = e;
        #pragma unroll
        for (int off = 8; off; off >>= 1)
            ssum += __shfl_xor_sync(0xffffffffu, ssum, off);
        float wv = e * frcp(ssum) * DESCALE;    // fold 1/sum + undo HSCALE
        if (lane < 16) wsm2[ql * 16 + lane] = pack2(wv, wv);
    }
    __syncthreads();

    // ---- epilogue: thread handles 2 queries x 2 columns ----
    const int qset = tid >> 7;                  // 0..3 -> queries qset*2, qset*2+1
    const int c2   = tid & 127;                 // u2 column within half
    u64 oA0[2], oA1[2], oB0[2], oB1[2];
    #pragma unroll
    for (int q = 0; q < 2; ++q) { oA0[q]=0ULL; oA1[q]=0ULL; oB0[q]=0ULL; oB1[q]=0ULL; }

    #pragma unroll
    for (int rp = 0; rp < 8; ++rp) {            // row pairs
        ulonglong2 wq[2];
        #pragma unroll
        for (int q = 0; q < 2; ++q)
            wq[q] = ((const ulonglong2*)(wsm2 + (qset * 2 + q) * 16))[rp];
        ulonglong2 vaA = cs_u2[(2 * rp)     * (D_DIM / 4) + c2];
        ulonglong2 vbA = cs_u2[(2 * rp + 1) * (D_DIM / 4) + c2];
        ulonglong2 vaB = cs_u2[(2 * rp)     * (D_DIM / 4) + 128 + c2];
        ulonglong2 vbB = cs_u2[(2 * rp + 1) * (D_DIM / 4) + 128 + c2];
        #pragma unroll
        for (int q = 0; q < 2; ++q) {
            oA0[q] = fma2(wq[q].x, vaA.x, oA0[q]);
            oA1[q] = fma2(wq[q].x, vaA.y, oA1[q]);
            oA0[q] = fma2(wq[q].y, vbA.x, oA0[q]);
            oA1[q] = fma2(wq[q].y, vbA.y, oA1[q]);
            oB0[q] = fma2(wq[q].x, vaB.x, oB0[q]);
            oB1[q] = fma2(wq[q].x, vaB.y, oB1[q]);
            oB0[q] = fma2(wq[q].y, vbB.x, oB0[q]);
            oB1[q] = fma2(wq[q].y, vbB.y, oB1[q]);
        }
    }

    #pragma unroll
    for (int q = 0; q < 2; ++q) {
        const int qg = qb * QB + qset * 2 + q;
        ulonglong2* og = (ulonglong2*)(out + ((size_t)qg * C_CLASS + c) * D_DIM);
        og[c2]       = make_ulonglong2(oA0[q], oA1[q]);
        og[128 + c2] = make_ulonglong2(oB0[q], oB1[q]);
    }
}

extern "C" void kernel_launch(void* const* d_in, const int* in_sizes, int n_in,
                              void* d_out, int out_size)
{
    (void)in_sizes; (void)n_in; (void)out_size;
    const float* data = (const float*)d_in[0];
    float* out = (float*)d_out;

    cudaFuncSetAttribute(instance_attention_kernel,
                         cudaFuncAttributeMaxDynamicSharedMemorySize, SMEM_BYTES);

    dim3 grid(512 / QB, C_CLASS);   // (64 query-blocks, 32 classes) = 2048 CTAs
    instance_attention_kernel<<<grid, THREADS, SMEM_BYTES>>>(data, out);
}